// round 10
// baseline (speedup 1.0000x reference)
#include <cuda_runtime.h>
#include <cuda_fp16.h>
#include <math.h>

#define NN 100000
#define EE 800000
#define DH 128
#define DD 256
#define RPB 8             // rows per block = warps per block (fast path)
#define NB8 (NN / RPB)    // 12500
#define SCAN_B 1024
#define NBLK ((NN + SCAN_B - 1) / SCAN_B)   // 98

// bit-cast helpers
__device__ __forceinline__ unsigned int h2u(__half2 h) {
    return *reinterpret_cast<unsigned int*>(&h);
}
__device__ __forceinline__ __half2 u2h(unsigned int u) {
    return *reinterpret_cast<__half2*>(&u);
}
__device__ __forceinline__ float4 u2f4(uint2 hv) {
    float2 a = __half22float2(u2h(hv.x));
    float2 b = __half22float2(u2h(hv.y));
    return make_float4(a.x, a.y, b.x, b.y);
}
__device__ __forceinline__ uint2 f42u(float4 v) {
    uint2 r;
    r.x = h2u(__floats2half2_rn(v.x, v.y));
    r.y = h2u(__floats2half2_rn(v.z, v.w));
    return r;
}

// ------------- device-global scratch (no cudaMalloc allowed) -------------
__device__ float  g_acc[(size_t)NN * DH];   // fp32 RK4 accumulator
__device__ __half g_h0 [(size_t)NN * DH];   // z high half (fp16, gather mirror)
__device__ __half g_zl [(size_t)NN * DH];   // z residual (fp16): z ~= h0 + zl
__device__ __half g_t1 [(size_t)NN * DH];   // t1 / t3 (fp16)
__device__ __half g_t2 [(size_t)NN * DH];   // t2 (fp16)
__device__ __half g_kh [(size_t)NN * DH];   // k3 (fp16)
__device__ __half g_xh [(size_t)NN * DH];   // fp16 mirror of x
// fallback (general M) buffers, layout [N,256]
__device__ float g_w0[(size_t)NN * DD];
__device__ float g_w1[(size_t)NN * DD];
__device__ float g_w2[(size_t)NN * DD];
__device__ float g_wk[(size_t)NN * DD];
__device__ float g_alpha[NN];
__device__ float g_hb[NN * 2];
__device__ float g_M[DD * DD];
__device__ int   g_mflag;
__device__ int   g_rowptr[NN + 1];
__device__ int   g_cnt[NN];
__device__ int   g_bsum[NBLK];
__device__ unsigned long long g_edges[EE]; // hi32 = val bits, lo32 = col

// ------------------- setup kernels -------------------
__global__ void reset_all() {
    int i = blockIdx.x * blockDim.x + threadIdx.x;
    if (i == 0) g_mflag = 0;
    if (i < NN) g_cnt[i] = 0;
}

__global__ void computeM_small(const float* __restrict__ W, const float* __restrict__ dvec,
                               const float* __restrict__ alpha0, const float* __restrict__ h,
                               const float* __restrict__ Whh, const float* __restrict__ bih,
                               const float* __restrict__ bhh) {
    if (blockIdx.x < DD) {
        int i = blockIdx.x, j = threadIdx.x;
        float s = 0.0f;
        for (int k = 0; k < DD; ++k) {
            float d = fminf(fmaxf(dvec[k], 0.0f), 1.0f);
            s += W[i * DD + k] * d * W[j * DD + k];
        }
        float m = s - ((i == j) ? 1.0f : 0.0f);
        g_M[i * DD + j] = m;
        if (m != 0.0f) atomicOr(&g_mflag, 1);
    } else {
        int i = (blockIdx.x - DD) * blockDim.x + threadIdx.x;
        if (i < NN) {
            g_alpha[i] = alpha0[i];
            float h0 = h[2 * i], h1 = h[2 * i + 1];
            g_hb[2 * i]     = h0 * Whh[0] + h1 * Whh[1] + bih[0] + bhh[0];
            g_hb[2 * i + 1] = h0 * Whh[2] + h1 * Whh[3] + bih[1] + bhh[1];
        }
    }
}

__global__ void count_k(const int* __restrict__ rows) {
    int i = blockIdx.x * blockDim.x + threadIdx.x;
    if (i < EE) atomicAdd(&g_cnt[rows[i]], 1);
}

__global__ void scan_initz(const float* __restrict__ x) {
    if (blockIdx.x < NBLK) {
        __shared__ int buf[SCAN_B];
        int idx = blockIdx.x * SCAN_B + (int)threadIdx.x;
        int v = (idx < NN) ? g_cnt[idx] : 0;
        buf[threadIdx.x] = v;
        __syncthreads();
        for (int off = 1; off < SCAN_B; off <<= 1) {
            int tv = (threadIdx.x >= off) ? buf[threadIdx.x - off] : 0;
            __syncthreads();
            buf[threadIdx.x] += tv;
            __syncthreads();
        }
        if (idx < NN) g_rowptr[idx] = buf[threadIdx.x] - v;
        if (threadIdx.x == SCAN_B - 1) g_bsum[blockIdx.x] = buf[SCAN_B - 1];
    } else {
        int i = (blockIdx.x - NBLK) * SCAN_B + (int)threadIdx.x;  // over NN*DH/4
        if (i < NN * DH / 4) {
            float4 v = ((const float4*)x)[i];
            if (!g_mflag) {
                uint2 hh = f42u(v);
                ((uint2*)g_h0)[i] = hh;
                ((uint2*)g_xh)[i] = hh;
                float4 h4 = u2f4(hh);
                float4 rl;
                rl.x = v.x - h4.x; rl.y = v.y - h4.y;
                rl.z = v.z - h4.z; rl.w = v.w - h4.w;
                ((uint2*)g_zl)[i] = f42u(rl);
            } else {
                int r = i >> 5, c = (i & 31) * 4;
                float4* w = (float4*)(g_w0 + (size_t)r * DD);
                w[c / 4] = v;
                w[(DH + c) / 4] = make_float4(0.f, 0.f, 0.f, 0.f);
            }
        }
    }
}

__global__ void scan_bsum() {
    __shared__ int b[128];
    int v = ((int)threadIdx.x < NBLK) ? g_bsum[threadIdx.x] : 0;
    b[threadIdx.x] = v;
    __syncthreads();
    for (int off = 1; off < 128; off <<= 1) {
        int tv = (threadIdx.x >= off) ? b[threadIdx.x - off] : 0;
        __syncthreads();
        b[threadIdx.x] += tv;
        __syncthreads();
    }
    if ((int)threadIdx.x < NBLK) g_bsum[threadIdx.x] = b[threadIdx.x] - v;
    if (threadIdx.x == 127) g_rowptr[NN] = b[127];
}

__global__ void scan_add_zero() {
    int i = blockIdx.x * blockDim.x + threadIdx.x;
    if (i < NN) {
        g_rowptr[i] += g_bsum[i >> 10];
        g_cnt[i] = 0;
    }
}

__global__ void scatter_k(const int* __restrict__ rows, const int* __restrict__ cols,
                          const float* __restrict__ vals) {
    int i = blockIdx.x * blockDim.x + threadIdx.x;
    if (i < EE) {
        int r = rows[i];
        int pos = g_rowptr[r] + atomicAdd(&g_cnt[r], 1);
        g_edges[pos] = ((unsigned long long)__float_as_uint(vals[i]) << 32)
                       | (unsigned int)cols[i];
    }
}

// ------------------- fused ODE eval (one RK4 stage) -------------------
// Fast path: warp-per-row, 32 lanes x 4 cols; all per-row stream loads
// hoisted before the gather so they overlap its latency.
__global__ __launch_bounds__(256, 3) void ode_eval(int stage,
    const float* __restrict__ x, const float* __restrict__ Wih,
    float* __restrict__ out)
{
    const float hdt = 0.225f, dt = 0.45f, dt3 = 0.15f, dt6 = 0.075f;
    int t = threadIdx.x;

    if (!g_mflag) {
        int wrp = t >> 5, lane = t & 31;
        int r = blockIdx.x * RPB + wrp;
        const __half* zin = (stage == 1) ? g_h0 : (stage == 3) ? g_t2 : g_t1;
        size_t r4 = (size_t)r * (DH / 4) + lane;     // uint2/float4 index

        // ---- round 1: issue ALL per-row loads up front ----
        int es = g_rowptr[r], ee = g_rowptr[r + 1];
        uint2 zvu = ((const uint2*)zin)[r4];
        uint2 xhu = ((const uint2*)g_xh)[r4];
        float alpha_old = g_alpha[r];
        float hb0 = g_hb[2 * r], hb1 = g_hb[2 * r + 1];
        uint2 aux1u = make_uint2(0u, 0u), aux2u = make_uint2(0u, 0u);
        float4 accv = make_float4(0.f, 0.f, 0.f, 0.f);
        if (stage == 2) {
            aux1u = ((const uint2*)g_h0)[r4];
            aux2u = ((const uint2*)g_zl)[r4];
        } else if (stage == 3) {
            aux1u = ((const uint2*)g_h0)[r4];
        } else if (stage == 4) {
            accv  = ((const float4*)g_acc)[r4];
            aux1u = ((const uint2*)g_kh)[r4];
        }

        float4 zv = u2f4(zvu);

        // gate dots -> all-lanes butterfly (overlaps edge-descriptor fetch)
        float4 w0 = ((const float4*)Wih)[lane];
        float4 w1 = ((const float4*)(Wih + DD))[lane];
        float d0 = zv.x * w0.x + zv.y * w0.y + zv.z * w0.z + zv.w * w0.w;
        float d1 = zv.x * w1.x + zv.y * w1.y + zv.z * w1.z + zv.w * w1.w;
        #pragma unroll
        for (int off = 16; off; off >>= 1) {
            d0 += __shfl_xor_sync(0xffffffffu, d0, off);
            d1 += __shfl_xor_sync(0xffffffffu, d1, off);
        }
        float a0 = tanhf(d0 + hb0);
        float a1 = tanhf(d1 + hb1);
        float al = alpha_old * a0 + a1;
        if (lane == 0) g_alpha[r] = al;
        al = 1.0f / (1.0f + expf(-al));

        // SpMM gather: two-phase, 8 loads in flight
        float4 az = make_float4(0.f, 0.f, 0.f, 0.f);
        int i = es;
        for (; i + 8 <= ee; i += 8) {
            unsigned long long p[8];
            #pragma unroll
            for (int j = 0; j < 8; ++j) p[j] = g_edges[i + j];
            uint2 hv[8];
            #pragma unroll
            for (int j = 0; j < 8; ++j) {
                int c = (int)(unsigned int)(p[j] & 0xffffffffu);
                hv[j] = ((const uint2*)zin)[(size_t)c * (DH / 4) + lane];
            }
            #pragma unroll
            for (int j = 0; j < 8; ++j) {
                float v = __uint_as_float((unsigned int)(p[j] >> 32));
                float2 a = __half22float2(u2h(hv[j].x));
                float2 b = __half22float2(u2h(hv[j].y));
                az.x += v * a.x; az.y += v * a.y; az.z += v * b.x; az.w += v * b.y;
            }
        }
        if (i + 4 <= ee) {
            unsigned long long p[4];
            #pragma unroll
            for (int j = 0; j < 4; ++j) p[j] = g_edges[i + j];
            uint2 hv[4];
            #pragma unroll
            for (int j = 0; j < 4; ++j) {
                int c = (int)(unsigned int)(p[j] & 0xffffffffu);
                hv[j] = ((const uint2*)zin)[(size_t)c * (DH / 4) + lane];
            }
            #pragma unroll
            for (int j = 0; j < 4; ++j) {
                float v = __uint_as_float((unsigned int)(p[j] >> 32));
                float2 a = __half22float2(u2h(hv[j].x));
                float2 b = __half22float2(u2h(hv[j].y));
                az.x += v * a.x; az.y += v * a.y; az.z += v * b.x; az.w += v * b.y;
            }
            i += 4;
        }
        for (; i < ee; ++i) {
            unsigned long long pk = g_edges[i];
            int   c = (int)(unsigned int)(pk & 0xffffffffu);
            float v = __uint_as_float((unsigned int)(pk >> 32));
            uint2 hv = ((const uint2*)zin)[(size_t)c * (DH / 4) + lane];
            float2 a = __half22float2(u2h(hv.x));
            float2 b = __half22float2(u2h(hv.y));
            az.x += v * a.x; az.y += v * a.y; az.z += v * b.x; az.w += v * b.y;
        }

        float4 x4 = u2f4(xhu);
        float4 f;
        f.x = al * 0.5f * (az.x - zv.x) + x4.x;
        f.y = al * 0.5f * (az.y - zv.y) + x4.y;
        f.z = al * 0.5f * (az.z - zv.z) + x4.z;
        f.w = al * 0.5f * (az.w - zv.w) + x4.w;

        if (stage == 1) {
            float4 t1;
            t1.x = zv.x + hdt * f.x; t1.y = zv.y + hdt * f.y;
            t1.z = zv.z + hdt * f.z; t1.w = zv.w + hdt * f.w;
            ((uint2*)g_t1)[r4] = f42u(t1);
        } else if (stage == 2) {
            float4 zh = u2f4(aux1u);
            float4 zr = u2f4(aux2u);
            float4 z0;
            z0.x = zh.x + zr.x; z0.y = zh.y + zr.y;
            z0.z = zh.z + zr.z; z0.w = zh.w + zr.w;
            const float ih = 1.0f / 0.225f;
            float4 k1;
            k1.x = (zv.x - z0.x) * ih; k1.y = (zv.y - z0.y) * ih;
            k1.z = (zv.z - z0.z) * ih; k1.w = (zv.w - z0.w) * ih;
            float4 t2;
            t2.x = z0.x + hdt * f.x; t2.y = z0.y + hdt * f.y;
            t2.z = z0.z + hdt * f.z; t2.w = z0.w + hdt * f.w;
            ((uint2*)g_t2)[r4] = f42u(t2);
            float4 ac;
            ac.x = z0.x + dt6 * k1.x + dt3 * f.x;
            ac.y = z0.y + dt6 * k1.y + dt3 * f.y;
            ac.z = z0.z + dt6 * k1.z + dt3 * f.z;
            ac.w = z0.w + dt6 * k1.w + dt3 * f.w;
            ((float4*)g_acc)[r4] = ac;
        } else if (stage == 3) {
            float4 z0 = u2f4(aux1u);
            float4 t3;
            t3.x = z0.x + dt * f.x; t3.y = z0.y + dt * f.y;
            t3.z = z0.z + dt * f.z; t3.w = z0.w + dt * f.w;
            ((uint2*)g_t1)[r4] = f42u(t3);
            ((uint2*)g_kh)[r4] = f42u(f);
        } else {
            float4 k3 = u2f4(aux1u);
            float4 zn;
            zn.x = accv.x + dt3 * k3.x + dt6 * f.x;
            zn.y = accv.y + dt3 * k3.y + dt6 * f.y;
            zn.z = accv.z + dt3 * k3.z + dt6 * f.z;
            zn.w = accv.w + dt3 * k3.w + dt6 * f.w;
            if (out != nullptr) {
                ((float4*)out)[r4] = zn;
            } else {
                uint2 hh = f42u(zn);
                ((uint2*)g_h0)[r4] = hh;
                float4 h4 = u2f4(hh);
                float4 rl;
                rl.x = zn.x - h4.x; rl.y = zn.y - h4.y;
                rl.z = zn.z - h4.z; rl.w = zn.w - h4.w;
                ((uint2*)g_zl)[r4] = f42u(rl);
            }
        }
    } else {
        // -------- general fallback (never taken for given inputs) --------
        __shared__ float s0[8], s1v[8], s_al[1];
        int w = t >> 5, l = t & 31;
        for (int rr = 0; rr < RPB; ++rr) {
            int r = blockIdx.x * RPB + rr;
            const float* zin = (stage == 1) ? g_w0 : (stage == 2) ? g_w1
                             : (stage == 3) ? g_w2 : g_w1;
            size_t ri = (size_t)r * DD + t;
            float zv = zin[ri];
            float d0 = zv * Wih[t];
            float d1 = zv * Wih[DD + t];
            #pragma unroll
            for (int off = 16; off; off >>= 1) {
                d0 += __shfl_down_sync(0xffffffffu, d0, off);
                d1 += __shfl_down_sync(0xffffffffu, d1, off);
            }
            if (l == 0) { s0[w] = d0; s1v[w] = d1; }
            __syncthreads();
            if (t == 0) {
                float a0 = 0.0f, a1 = 0.0f;
                #pragma unroll
                for (int i = 0; i < 8; ++i) { a0 += s0[i]; a1 += s1v[i]; }
                a0 = tanhf(a0 + g_hb[2 * r]);
                a1 = tanhf(a1 + g_hb[2 * r + 1]);
                float al = g_alpha[r] * a0 + a1;
                g_alpha[r] = al;
                s_al[0] = 1.0f / (1.0f + expf(-al));
            }
            int es = g_rowptr[r], ee = g_rowptr[r + 1];
            float az = 0.0f;
            for (int i = es; i < ee; ++i) {
                unsigned long long pk = g_edges[i];
                int   c = (int)(unsigned int)(pk & 0xffffffffu);
                float v = __uint_as_float((unsigned int)(pk >> 32));
                az += v * zin[(size_t)c * DD + t];
            }
            __syncthreads();
            float f = s_al[0] * 0.5f * (az - zv) + ((t < DH) ? x[(size_t)r * DH + t] : 0.0f);
            const float* zr = zin + (size_t)r * DD;
            for (int j = 0; j < DD; ++j) f += zr[j] * g_M[j * DD + t];

            if (stage == 1)      { g_wk[ri] = f;          g_w1[ri] = zv + hdt * f; }
            else if (stage == 2) { g_wk[ri] += 2.0f * f;  g_w2[ri] = g_w0[ri] + hdt * f; }
            else if (stage == 3) { g_wk[ri] += 2.0f * f;  g_w1[ri] = g_w0[ri] + dt * f; }
            else {
                float zn = g_w0[ri] + dt6 * (g_wk[ri] + f);
                g_w0[ri] = zn;
                if (out != nullptr && t < DH) out[(size_t)r * DH + t] = zn;
            }
            __syncthreads();
        }
    }
}

// ------------------- launch -------------------
extern "C" void kernel_launch(void* const* d_in, const int* in_sizes, int n_in,
                              void* d_out, int out_size) {
    const float* x      = (const float*)d_in[0];
    const int*   erows  = (const int*)  d_in[1];
    const int*   ecols  = (const int*)  d_in[2];
    const float* evals  = (const float*)d_in[3];
    const float* Wih    = (const float*)d_in[4];
    const float* Whh    = (const float*)d_in[5];
    const float* bih    = (const float*)d_in[6];
    const float* bhh    = (const float*)d_in[7];
    const float* h      = (const float*)d_in[8];
    const float* alpha0 = (const float*)d_in[9];
    const float* W      = (const float*)d_in[10];
    const float* dvec   = (const float*)d_in[11];
    float* out = (float*)d_out;

    reset_all<<<(NN + 255) / 256, 256>>>();
    computeM_small<<<DD + (NN + 255) / 256, 256>>>(W, dvec, alpha0, h, Whh, bih, bhh);
    count_k<<<(EE + 255) / 256, 256>>>(erows);
    scan_initz<<<NBLK + (NN * DH / 4 + SCAN_B - 1) / SCAN_B, SCAN_B>>>(x);
    scan_bsum<<<1, 128>>>();
    scan_add_zero<<<(NN + 255) / 256, 256>>>();
    scatter_k<<<(EE + 255) / 256, 256>>>(erows, ecols, evals);

    for (int s = 0; s < 2; ++s) {
        float* last_out = (s == 1) ? out : nullptr;
        ode_eval<<<NB8, 256>>>(1, x, Wih, nullptr);
        ode_eval<<<NB8, 256>>>(2, x, Wih, nullptr);
        ode_eval<<<NB8, 256>>>(3, x, Wih, nullptr);
        ode_eval<<<NB8, 256>>>(4, x, Wih, last_out);
    }
}

// round 11
// speedup vs baseline: 1.1972x; 1.1972x over previous
#include <cuda_runtime.h>
#include <cuda_fp16.h>
#include <math.h>

#define NN 100000
#define EE 800000
#define DH 128
#define DD 256
#define RPB 8             // rows per block = warps per block (fast path)
#define NB8 (NN / RPB)    // 12500
#define SCAN_B 1024
#define NBLK ((NN + SCAN_B - 1) / SCAN_B)   // 98

// bit-cast helpers
__device__ __forceinline__ unsigned int h2u(__half2 h) {
    return *reinterpret_cast<unsigned int*>(&h);
}
__device__ __forceinline__ __half2 u2h(unsigned int u) {
    return *reinterpret_cast<__half2*>(&u);
}
__device__ __forceinline__ float4 u2f4(uint2 hv) {
    float2 a = __half22float2(u2h(hv.x));
    float2 b = __half22float2(u2h(hv.y));
    return make_float4(a.x, a.y, b.x, b.y);
}
__device__ __forceinline__ uint2 f42u(float4 v) {
    uint2 r;
    r.x = h2u(__floats2half2_rn(v.x, v.y));
    r.y = h2u(__floats2half2_rn(v.z, v.w));
    return r;
}

// ------------- device-global scratch (no cudaMalloc allowed) -------------
__device__ float  g_acc[(size_t)NN * DH];   // fp32 RK4 accumulator
__device__ __half g_h0 [(size_t)NN * DH];   // z high half (fp16, gather mirror)
__device__ __half g_zl [(size_t)NN * DH];   // z residual (fp16): z ~= h0 + zl
__device__ __half g_t1 [(size_t)NN * DH];   // t1 / t3 (fp16)
__device__ __half g_t2 [(size_t)NN * DH];   // t2 (fp16)
__device__ __half g_kh [(size_t)NN * DH];   // k3 (fp16)
__device__ __half g_xh [(size_t)NN * DH];   // fp16 mirror of x
// fallback (general M) buffers, layout [N,256]
__device__ float g_w0[(size_t)NN * DD];
__device__ float g_w1[(size_t)NN * DD];
__device__ float g_w2[(size_t)NN * DD];
__device__ float g_wk[(size_t)NN * DD];
__device__ float g_alpha[NN];
__device__ float g_hb[NN * 2];
__device__ float g_M[DD * DD];
__device__ int   g_mflag;
__device__ int   g_rowptr[NN + 1];
__device__ int   g_cnt[NN];
__device__ int   g_bsum[NBLK];
__device__ unsigned long long g_edges[EE]; // hi32 = val bits, lo32 = col

// ------------------- setup kernels -------------------
__global__ void reset_all() {
    int i = blockIdx.x * blockDim.x + threadIdx.x;
    if (i == 0) g_mflag = 0;
    if (i < NN) g_cnt[i] = 0;
}

__global__ void computeM_small(const float* __restrict__ W, const float* __restrict__ dvec,
                               const float* __restrict__ alpha0, const float* __restrict__ h,
                               const float* __restrict__ Whh, const float* __restrict__ bih,
                               const float* __restrict__ bhh) {
    if (blockIdx.x < DD) {
        int i = blockIdx.x, j = threadIdx.x;
        float s = 0.0f;
        for (int k = 0; k < DD; ++k) {
            float d = fminf(fmaxf(dvec[k], 0.0f), 1.0f);
            s += W[i * DD + k] * d * W[j * DD + k];
        }
        float m = s - ((i == j) ? 1.0f : 0.0f);
        g_M[i * DD + j] = m;
        if (m != 0.0f) atomicOr(&g_mflag, 1);
    } else {
        int i = (blockIdx.x - DD) * blockDim.x + threadIdx.x;
        if (i < NN) {
            g_alpha[i] = alpha0[i];
            float h0 = h[2 * i], h1 = h[2 * i + 1];
            g_hb[2 * i]     = h0 * Whh[0] + h1 * Whh[1] + bih[0] + bhh[0];
            g_hb[2 * i + 1] = h0 * Whh[2] + h1 * Whh[3] + bih[1] + bhh[1];
        }
    }
}

__global__ void count_k(const int* __restrict__ rows) {
    int i = blockIdx.x * blockDim.x + threadIdx.x;
    if (i < EE) atomicAdd(&g_cnt[rows[i]], 1);
}

__global__ void scan_initz(const float* __restrict__ x) {
    if (blockIdx.x < NBLK) {
        __shared__ int buf[SCAN_B];
        int idx = blockIdx.x * SCAN_B + (int)threadIdx.x;
        int v = (idx < NN) ? g_cnt[idx] : 0;
        buf[threadIdx.x] = v;
        __syncthreads();
        for (int off = 1; off < SCAN_B; off <<= 1) {
            int tv = (threadIdx.x >= off) ? buf[threadIdx.x - off] : 0;
            __syncthreads();
            buf[threadIdx.x] += tv;
            __syncthreads();
        }
        if (idx < NN) g_rowptr[idx] = buf[threadIdx.x] - v;
        if (threadIdx.x == SCAN_B - 1) g_bsum[blockIdx.x] = buf[SCAN_B - 1];
    } else {
        int i = (blockIdx.x - NBLK) * SCAN_B + (int)threadIdx.x;  // over NN*DH/4
        if (i < NN * DH / 4) {
            float4 v = ((const float4*)x)[i];
            if (!g_mflag) {
                uint2 hh = f42u(v);
                ((uint2*)g_h0)[i] = hh;
                ((uint2*)g_xh)[i] = hh;
                float4 h4 = u2f4(hh);
                float4 rl;
                rl.x = v.x - h4.x; rl.y = v.y - h4.y;
                rl.z = v.z - h4.z; rl.w = v.w - h4.w;
                ((uint2*)g_zl)[i] = f42u(rl);
            } else {
                int r = i >> 5, c = (i & 31) * 4;
                float4* w = (float4*)(g_w0 + (size_t)r * DD);
                w[c / 4] = v;
                w[(DH + c) / 4] = make_float4(0.f, 0.f, 0.f, 0.f);
            }
        }
    }
}

__global__ void scan_bsum() {
    __shared__ int b[128];
    int v = ((int)threadIdx.x < NBLK) ? g_bsum[threadIdx.x] : 0;
    b[threadIdx.x] = v;
    __syncthreads();
    for (int off = 1; off < 128; off <<= 1) {
        int tv = (threadIdx.x >= off) ? b[threadIdx.x - off] : 0;
        __syncthreads();
        b[threadIdx.x] += tv;
        __syncthreads();
    }
    if ((int)threadIdx.x < NBLK) g_bsum[threadIdx.x] = b[threadIdx.x] - v;
    if (threadIdx.x == 127) g_rowptr[NN] = b[127];
}

__global__ void scan_add_zero() {
    int i = blockIdx.x * blockDim.x + threadIdx.x;
    if (i < NN) {
        g_rowptr[i] += g_bsum[i >> 10];
        g_cnt[i] = 0;
    }
}

__global__ void scatter_k(const int* __restrict__ rows, const int* __restrict__ cols,
                          const float* __restrict__ vals) {
    int i = blockIdx.x * blockDim.x + threadIdx.x;
    if (i < EE) {
        int r = rows[i];
        int pos = g_rowptr[r] + atomicAdd(&g_cnt[r], 1);
        g_edges[pos] = ((unsigned long long)__float_as_uint(vals[i]) << 32)
                       | (unsigned int)cols[i];
    }
}

// ------------------- fused ODE eval (one RK4 stage) -------------------
// Fast path: warp-per-row, 32 lanes x 4 cols; per-row stream loads hoisted,
// NO occupancy clause (avoid forced register cap -> spills in gather loop).
__global__ __launch_bounds__(256) void ode_eval(int stage,
    const float* __restrict__ x, const float* __restrict__ Wih,
    float* __restrict__ out)
{
    const float hdt = 0.225f, dt = 0.45f, dt3 = 0.15f, dt6 = 0.075f;
    int t = threadIdx.x;

    if (!g_mflag) {
        int wrp = t >> 5, lane = t & 31;
        int r = blockIdx.x * RPB + wrp;
        const __half* zin = (stage == 1) ? g_h0 : (stage == 3) ? g_t2 : g_t1;
        size_t r4 = (size_t)r * (DH / 4) + lane;     // uint2/float4 index

        // ---- issue per-row loads up front ----
        int es = g_rowptr[r], ee = g_rowptr[r + 1];
        uint2 zvu = ((const uint2*)zin)[r4];
        uint2 xhu = ((const uint2*)g_xh)[r4];
        float alpha_old = g_alpha[r];
        float hb0 = g_hb[2 * r], hb1 = g_hb[2 * r + 1];
        uint2 aux1u = make_uint2(0u, 0u), aux2u = make_uint2(0u, 0u);
        float4 accv = make_float4(0.f, 0.f, 0.f, 0.f);
        if (stage == 2) {
            aux1u = ((const uint2*)g_h0)[r4];
            aux2u = ((const uint2*)g_zl)[r4];
        } else if (stage == 3) {
            aux1u = ((const uint2*)g_h0)[r4];
        } else if (stage == 4) {
            accv  = ((const float4*)g_acc)[r4];
            aux1u = ((const uint2*)g_kh)[r4];
        }

        float4 zv = u2f4(zvu);

        // gate dots -> all-lanes butterfly (overlaps edge-descriptor fetch)
        float4 w0 = ((const float4*)Wih)[lane];
        float4 w1 = ((const float4*)(Wih + DD))[lane];
        float d0 = zv.x * w0.x + zv.y * w0.y + zv.z * w0.z + zv.w * w0.w;
        float d1 = zv.x * w1.x + zv.y * w1.y + zv.z * w1.z + zv.w * w1.w;
        #pragma unroll
        for (int off = 16; off; off >>= 1) {
            d0 += __shfl_xor_sync(0xffffffffu, d0, off);
            d1 += __shfl_xor_sync(0xffffffffu, d1, off);
        }
        float a0 = tanhf(d0 + hb0);
        float a1 = tanhf(d1 + hb1);
        float al = alpha_old * a0 + a1;
        if (lane == 0) g_alpha[r] = al;
        al = 1.0f / (1.0f + expf(-al));

        // SpMM gather: two-phase, 8 loads in flight
        float4 az = make_float4(0.f, 0.f, 0.f, 0.f);
        int i = es;
        for (; i + 8 <= ee; i += 8) {
            unsigned long long p[8];
            #pragma unroll
            for (int j = 0; j < 8; ++j) p[j] = g_edges[i + j];
            uint2 hv[8];
            #pragma unroll
            for (int j = 0; j < 8; ++j) {
                int c = (int)(unsigned int)(p[j] & 0xffffffffu);
                hv[j] = ((const uint2*)zin)[(size_t)c * (DH / 4) + lane];
            }
            #pragma unroll
            for (int j = 0; j < 8; ++j) {
                float v = __uint_as_float((unsigned int)(p[j] >> 32));
                float2 a = __half22float2(u2h(hv[j].x));
                float2 b = __half22float2(u2h(hv[j].y));
                az.x += v * a.x; az.y += v * a.y; az.z += v * b.x; az.w += v * b.y;
            }
        }
        if (i + 4 <= ee) {
            unsigned long long p[4];
            #pragma unroll
            for (int j = 0; j < 4; ++j) p[j] = g_edges[i + j];
            uint2 hv[4];
            #pragma unroll
            for (int j = 0; j < 4; ++j) {
                int c = (int)(unsigned int)(p[j] & 0xffffffffu);
                hv[j] = ((const uint2*)zin)[(size_t)c * (DH / 4) + lane];
            }
            #pragma unroll
            for (int j = 0; j < 4; ++j) {
                float v = __uint_as_float((unsigned int)(p[j] >> 32));
                float2 a = __half22float2(u2h(hv[j].x));
                float2 b = __half22float2(u2h(hv[j].y));
                az.x += v * a.x; az.y += v * a.y; az.z += v * b.x; az.w += v * b.y;
            }
            i += 4;
        }
        for (; i < ee; ++i) {
            unsigned long long pk = g_edges[i];
            int   c = (int)(unsigned int)(pk & 0xffffffffu);
            float v = __uint_as_float((unsigned int)(pk >> 32));
            uint2 hv = ((const uint2*)zin)[(size_t)c * (DH / 4) + lane];
            float2 a = __half22float2(u2h(hv.x));
            float2 b = __half22float2(u2h(hv.y));
            az.x += v * a.x; az.y += v * a.y; az.z += v * b.x; az.w += v * b.y;
        }

        float4 x4 = u2f4(xhu);
        float4 f;
        f.x = al * 0.5f * (az.x - zv.x) + x4.x;
        f.y = al * 0.5f * (az.y - zv.y) + x4.y;
        f.z = al * 0.5f * (az.z - zv.z) + x4.z;
        f.w = al * 0.5f * (az.w - zv.w) + x4.w;

        if (stage == 1) {
            float4 t1;
            t1.x = zv.x + hdt * f.x; t1.y = zv.y + hdt * f.y;
            t1.z = zv.z + hdt * f.z; t1.w = zv.w + hdt * f.w;
            ((uint2*)g_t1)[r4] = f42u(t1);
        } else if (stage == 2) {
            float4 zh = u2f4(aux1u);
            float4 zr = u2f4(aux2u);
            float4 z0;
            z0.x = zh.x + zr.x; z0.y = zh.y + zr.y;
            z0.z = zh.z + zr.z; z0.w = zh.w + zr.w;
            const float ih = 1.0f / 0.225f;
            float4 k1;
            k1.x = (zv.x - z0.x) * ih; k1.y = (zv.y - z0.y) * ih;
            k1.z = (zv.z - z0.z) * ih; k1.w = (zv.w - z0.w) * ih;
            float4 t2;
            t2.x = z0.x + hdt * f.x; t2.y = z0.y + hdt * f.y;
            t2.z = z0.z + hdt * f.z; t2.w = z0.w + hdt * f.w;
            ((uint2*)g_t2)[r4] = f42u(t2);
            float4 ac;
            ac.x = z0.x + dt6 * k1.x + dt3 * f.x;
            ac.y = z0.y + dt6 * k1.y + dt3 * f.y;
            ac.z = z0.z + dt6 * k1.z + dt3 * f.z;
            ac.w = z0.w + dt6 * k1.w + dt3 * f.w;
            ((float4*)g_acc)[r4] = ac;
        } else if (stage == 3) {
            float4 z0 = u2f4(aux1u);
            float4 t3;
            t3.x = z0.x + dt * f.x; t3.y = z0.y + dt * f.y;
            t3.z = z0.z + dt * f.z; t3.w = z0.w + dt * f.w;
            ((uint2*)g_t1)[r4] = f42u(t3);
            ((uint2*)g_kh)[r4] = f42u(f);
        } else {
            float4 k3 = u2f4(aux1u);
            float4 zn;
            zn.x = accv.x + dt3 * k3.x + dt6 * f.x;
            zn.y = accv.y + dt3 * k3.y + dt6 * f.y;
            zn.z = accv.z + dt3 * k3.z + dt6 * f.z;
            zn.w = accv.w + dt3 * k3.w + dt6 * f.w;
            if (out != nullptr) {
                ((float4*)out)[r4] = zn;
            } else {
                uint2 hh = f42u(zn);
                ((uint2*)g_h0)[r4] = hh;
                float4 h4 = u2f4(hh);
                float4 rl;
                rl.x = zn.x - h4.x; rl.y = zn.y - h4.y;
                rl.z = zn.z - h4.z; rl.w = zn.w - h4.w;
                ((uint2*)g_zl)[r4] = f42u(rl);
            }
        }
    } else {
        // -------- general fallback (never taken for given inputs) --------
        __shared__ float s0[8], s1v[8], s_al[1];
        int w = t >> 5, l = t & 31;
        for (int rr = 0; rr < RPB; ++rr) {
            int r = blockIdx.x * RPB + rr;
            const float* zin = (stage == 1) ? g_w0 : (stage == 2) ? g_w1
                             : (stage == 3) ? g_w2 : g_w1;
            size_t ri = (size_t)r * DD + t;
            float zv = zin[ri];
            float d0 = zv * Wih[t];
            float d1 = zv * Wih[DD + t];
            #pragma unroll
            for (int off = 16; off; off >>= 1) {
                d0 += __shfl_down_sync(0xffffffffu, d0, off);
                d1 += __shfl_down_sync(0xffffffffu, d1, off);
            }
            if (l == 0) { s0[w] = d0; s1v[w] = d1; }
            __syncthreads();
            if (t == 0) {
                float a0 = 0.0f, a1 = 0.0f;
                #pragma unroll
                for (int i = 0; i < 8; ++i) { a0 += s0[i]; a1 += s1v[i]; }
                a0 = tanhf(a0 + g_hb[2 * r]);
                a1 = tanhf(a1 + g_hb[2 * r + 1]);
                float al = g_alpha[r] * a0 + a1;
                g_alpha[r] = al;
                s_al[0] = 1.0f / (1.0f + expf(-al));
            }
            int es = g_rowptr[r], ee = g_rowptr[r + 1];
            float az = 0.0f;
            for (int i = es; i < ee; ++i) {
                unsigned long long pk = g_edges[i];
                int   c = (int)(unsigned int)(pk & 0xffffffffu);
                float v = __uint_as_float((unsigned int)(pk >> 32));
                az += v * zin[(size_t)c * DD + t];
            }
            __syncthreads();
            float f = s_al[0] * 0.5f * (az - zv) + ((t < DH) ? x[(size_t)r * DH + t] : 0.0f);
            const float* zr = zin + (size_t)r * DD;
            for (int j = 0; j < DD; ++j) f += zr[j] * g_M[j * DD + t];

            if (stage == 1)      { g_wk[ri] = f;          g_w1[ri] = zv + hdt * f; }
            else if (stage == 2) { g_wk[ri] += 2.0f * f;  g_w2[ri] = g_w0[ri] + hdt * f; }
            else if (stage == 3) { g_wk[ri] += 2.0f * f;  g_w1[ri] = g_w0[ri] + dt * f; }
            else {
                float zn = g_w0[ri] + dt6 * (g_wk[ri] + f);
                g_w0[ri] = zn;
                if (out != nullptr && t < DH) out[(size_t)r * DH + t] = zn;
            }
            __syncthreads();
        }
    }
}

// ------------------- launch -------------------
extern "C" void kernel_launch(void* const* d_in, const int* in_sizes, int n_in,
                              void* d_out, int out_size) {
    const float* x      = (const float*)d_in[0];
    const int*   erows  = (const int*)  d_in[1];
    const int*   ecols  = (const int*)  d_in[2];
    const float* evals  = (const float*)d_in[3];
    const float* Wih    = (const float*)d_in[4];
    const float* Whh    = (const float*)d_in[5];
    const float* bih    = (const float*)d_in[6];
    const float* bhh    = (const float*)d_in[7];
    const float* h      = (const float*)d_in[8];
    const float* alpha0 = (const float*)d_in[9];
    const float* W      = (const float*)d_in[10];
    const float* dvec   = (const float*)d_in[11];
    float* out = (float*)d_out;

    reset_all<<<(NN + 255) / 256, 256>>>();
    computeM_small<<<DD + (NN + 255) / 256, 256>>>(W, dvec, alpha0, h, Whh, bih, bhh);
    count_k<<<(EE + 255) / 256, 256>>>(erows);
    scan_initz<<<NBLK + (NN * DH / 4 + SCAN_B - 1) / SCAN_B, SCAN_B>>>(x);
    scan_bsum<<<1, 128>>>();
    scan_add_zero<<<(NN + 255) / 256, 256>>>();
    scatter_k<<<(EE + 255) / 256, 256>>>(erows, ecols, evals);

    for (int s = 0; s < 2; ++s) {
        float* last_out = (s == 1) ? out : nullptr;
        ode_eval<<<NB8, 256>>>(1, x, Wih, nullptr);
        ode_eval<<<NB8, 256>>>(2, x, Wih, nullptr);
        ode_eval<<<NB8, 256>>>(3, x, Wih, nullptr);
        ode_eval<<<NB8, 256>>>(4, x, Wih, last_out);
    }
}

// round 12
// speedup vs baseline: 1.3899x; 1.1609x over previous
#include <cuda_runtime.h>
#include <cuda_fp16.h>
#include <math.h>

#define NN 100000
#define EE 800000
#define DH 128
#define DD 256
#define RPB 8             // rows per block = warps per block (fast path)
#define NB8 (NN / RPB)    // 12500
#define SCAN_B 1024
#define NBLK ((NN + SCAN_B - 1) / SCAN_B)   // 98

// bit-cast helpers
__device__ __forceinline__ unsigned int h2u(__half2 h) {
    return *reinterpret_cast<unsigned int*>(&h);
}
__device__ __forceinline__ __half2 u2h(unsigned int u) {
    return *reinterpret_cast<__half2*>(&u);
}
__device__ __forceinline__ float4 u2f4(uint2 hv) {
    float2 a = __half22float2(u2h(hv.x));
    float2 b = __half22float2(u2h(hv.y));
    return make_float4(a.x, a.y, b.x, b.y);
}
__device__ __forceinline__ uint2 f42u(float4 v) {
    uint2 r;
    r.x = h2u(__floats2half2_rn(v.x, v.y));
    r.y = h2u(__floats2half2_rn(v.z, v.w));
    return r;
}

// ------------- device-global scratch (no cudaMalloc allowed) -------------
__device__ float  g_acc[(size_t)NN * DH];   // fp32 RK4 accumulator
__device__ __half g_h0 [(size_t)NN * DH];   // z high half (fp16, gather mirror)
__device__ __half g_zl [(size_t)NN * DH];   // z residual (fp16): z ~= h0 + zl
__device__ __half g_t1 [(size_t)NN * DH];   // t1 / t3 (fp16)
__device__ __half g_t2 [(size_t)NN * DH];   // t2 (fp16)
__device__ __half g_kh [(size_t)NN * DH];   // k3 (fp16)
__device__ __half g_xh [(size_t)NN * DH];   // fp16 mirror of x
// fallback (general M) buffers, layout [N,256]
__device__ float g_w0[(size_t)NN * DD];
__device__ float g_w1[(size_t)NN * DD];
__device__ float g_w2[(size_t)NN * DD];
__device__ float g_wk[(size_t)NN * DD];
__device__ float g_alpha[NN];
__device__ float g_hb[NN * 2];
__device__ float g_M[DD * DD];
__device__ int   g_mflag;
__device__ int   g_rowptr[NN + 1];
__device__ int   g_cnt[NN];
__device__ int   g_bsum[NBLK];
__device__ unsigned long long g_edges[EE]; // hi32 = val bits, lo32 = col

// ------------------- setup kernels -------------------
__global__ void reset_all() {
    int i = blockIdx.x * blockDim.x + threadIdx.x;
    if (i == 0) g_mflag = 0;
    if (i < NN) g_cnt[i] = 0;
}

__global__ void computeM_small(const float* __restrict__ W, const float* __restrict__ dvec,
                               const float* __restrict__ alpha0, const float* __restrict__ h,
                               const float* __restrict__ Whh, const float* __restrict__ bih,
                               const float* __restrict__ bhh) {
    if (blockIdx.x < DD) {
        int i = blockIdx.x, j = threadIdx.x;
        float s = 0.0f;
        for (int k = 0; k < DD; ++k) {
            float d = fminf(fmaxf(dvec[k], 0.0f), 1.0f);
            s += W[i * DD + k] * d * W[j * DD + k];
        }
        float m = s - ((i == j) ? 1.0f : 0.0f);
        g_M[i * DD + j] = m;
        if (m != 0.0f) atomicOr(&g_mflag, 1);
    } else {
        int i = (blockIdx.x - DD) * blockDim.x + threadIdx.x;
        if (i < NN) {
            g_alpha[i] = alpha0[i];
            float h0 = h[2 * i], h1 = h[2 * i + 1];
            g_hb[2 * i]     = h0 * Whh[0] + h1 * Whh[1] + bih[0] + bhh[0];
            g_hb[2 * i + 1] = h0 * Whh[2] + h1 * Whh[3] + bih[1] + bhh[1];
        }
    }
}

__global__ void count_k(const int* __restrict__ rows) {
    int i = blockIdx.x * blockDim.x + threadIdx.x;
    if (i < EE) atomicAdd(&g_cnt[rows[i]], 1);
}

__global__ void scan_initz(const float* __restrict__ x) {
    if (blockIdx.x < NBLK) {
        __shared__ int buf[SCAN_B];
        int idx = blockIdx.x * SCAN_B + (int)threadIdx.x;
        int v = (idx < NN) ? g_cnt[idx] : 0;
        buf[threadIdx.x] = v;
        __syncthreads();
        for (int off = 1; off < SCAN_B; off <<= 1) {
            int tv = (threadIdx.x >= off) ? buf[threadIdx.x - off] : 0;
            __syncthreads();
            buf[threadIdx.x] += tv;
            __syncthreads();
        }
        if (idx < NN) g_rowptr[idx] = buf[threadIdx.x] - v;
        if (threadIdx.x == SCAN_B - 1) g_bsum[blockIdx.x] = buf[SCAN_B - 1];
    } else {
        int i = (blockIdx.x - NBLK) * SCAN_B + (int)threadIdx.x;  // over NN*DH/4
        if (i < NN * DH / 4) {
            float4 v = ((const float4*)x)[i];
            if (!g_mflag) {
                uint2 hh = f42u(v);
                ((uint2*)g_h0)[i] = hh;
                ((uint2*)g_xh)[i] = hh;
                float4 h4 = u2f4(hh);
                float4 rl;
                rl.x = v.x - h4.x; rl.y = v.y - h4.y;
                rl.z = v.z - h4.z; rl.w = v.w - h4.w;
                ((uint2*)g_zl)[i] = f42u(rl);
            } else {
                int r = i >> 5, c = (i & 31) * 4;
                float4* w = (float4*)(g_w0 + (size_t)r * DD);
                w[c / 4] = v;
                w[(DH + c) / 4] = make_float4(0.f, 0.f, 0.f, 0.f);
            }
        }
    }
}

__global__ void scan_bsum() {
    __shared__ int b[128];
    int v = ((int)threadIdx.x < NBLK) ? g_bsum[threadIdx.x] : 0;
    b[threadIdx.x] = v;
    __syncthreads();
    for (int off = 1; off < 128; off <<= 1) {
        int tv = (threadIdx.x >= off) ? b[threadIdx.x - off] : 0;
        __syncthreads();
        b[threadIdx.x] += tv;
        __syncthreads();
    }
    if ((int)threadIdx.x < NBLK) g_bsum[threadIdx.x] = b[threadIdx.x] - v;
    if (threadIdx.x == 127) g_rowptr[NN] = b[127];
}

__global__ void scan_add_zero() {
    int i = blockIdx.x * blockDim.x + threadIdx.x;
    if (i < NN) {
        g_rowptr[i] += g_bsum[i >> 10];
        g_cnt[i] = 0;
    }
}

__global__ void scatter_k(const int* __restrict__ rows, const int* __restrict__ cols,
                          const float* __restrict__ vals) {
    int i = blockIdx.x * blockDim.x + threadIdx.x;
    if (i < EE) {
        int r = rows[i];
        int pos = g_rowptr[r] + atomicAdd(&g_cnt[r], 1);
        g_edges[pos] = ((unsigned long long)__float_as_uint(vals[i]) << 32)
                       | (unsigned int)cols[i];
    }
}

// ------------------- fused ODE eval (one RK4 stage) -------------------
// Fast path: warp-per-row, 32 lanes x 4 cols, 8-deep two-phase gather;
// STAGE is a compile-time parameter -> per-stage register allocation.
template<int STAGE>
__global__ __launch_bounds__(256) void ode_eval(
    const float* __restrict__ x, const float* __restrict__ Wih,
    float* __restrict__ out)
{
    const float hdt = 0.225f, dt = 0.45f, dt3 = 0.15f, dt6 = 0.075f;
    int t = threadIdx.x;

    if (!g_mflag) {
        int wrp = t >> 5, lane = t & 31;
        int r = blockIdx.x * RPB + wrp;
        const __half* zin = (STAGE == 1) ? g_h0 : (STAGE == 3) ? g_t2 : g_t1;
        size_t r4 = (size_t)r * (DH / 4) + lane;     // uint2/float4 index

        float4 zv = u2f4(((const uint2*)zin)[r4]);

        // gate dots -> all-lanes butterfly reduction
        float4 w0 = ((const float4*)Wih)[lane];
        float4 w1 = ((const float4*)(Wih + DD))[lane];
        float d0 = zv.x * w0.x + zv.y * w0.y + zv.z * w0.z + zv.w * w0.w;
        float d1 = zv.x * w1.x + zv.y * w1.y + zv.z * w1.z + zv.w * w1.w;
        #pragma unroll
        for (int off = 16; off; off >>= 1) {
            d0 += __shfl_xor_sync(0xffffffffu, d0, off);
            d1 += __shfl_xor_sync(0xffffffffu, d1, off);
        }
        float a0 = tanhf(d0 + g_hb[2 * r]);
        float a1 = tanhf(d1 + g_hb[2 * r + 1]);
        float al = g_alpha[r] * a0 + a1;
        if (lane == 0) g_alpha[r] = al;
        al = 1.0f / (1.0f + expf(-al));

        // SpMM gather: two-phase, 8 loads in flight
        int es = g_rowptr[r], ee = g_rowptr[r + 1];
        float4 az = make_float4(0.f, 0.f, 0.f, 0.f);
        int i = es;
        for (; i + 8 <= ee; i += 8) {
            unsigned long long p[8];
            #pragma unroll
            for (int j = 0; j < 8; ++j) p[j] = g_edges[i + j];
            uint2 hv[8];
            #pragma unroll
            for (int j = 0; j < 8; ++j) {
                int c = (int)(unsigned int)(p[j] & 0xffffffffu);
                hv[j] = ((const uint2*)zin)[(size_t)c * (DH / 4) + lane];
            }
            #pragma unroll
            for (int j = 0; j < 8; ++j) {
                float v = __uint_as_float((unsigned int)(p[j] >> 32));
                float2 a = __half22float2(u2h(hv[j].x));
                float2 b = __half22float2(u2h(hv[j].y));
                az.x += v * a.x; az.y += v * a.y; az.z += v * b.x; az.w += v * b.y;
            }
        }
        if (i + 4 <= ee) {
            unsigned long long p[4];
            #pragma unroll
            for (int j = 0; j < 4; ++j) p[j] = g_edges[i + j];
            uint2 hv[4];
            #pragma unroll
            for (int j = 0; j < 4; ++j) {
                int c = (int)(unsigned int)(p[j] & 0xffffffffu);
                hv[j] = ((const uint2*)zin)[(size_t)c * (DH / 4) + lane];
            }
            #pragma unroll
            for (int j = 0; j < 4; ++j) {
                float v = __uint_as_float((unsigned int)(p[j] >> 32));
                float2 a = __half22float2(u2h(hv[j].x));
                float2 b = __half22float2(u2h(hv[j].y));
                az.x += v * a.x; az.y += v * a.y; az.z += v * b.x; az.w += v * b.y;
            }
            i += 4;
        }
        for (; i < ee; ++i) {
            unsigned long long pk = g_edges[i];
            int   c = (int)(unsigned int)(pk & 0xffffffffu);
            float v = __uint_as_float((unsigned int)(pk >> 32));
            uint2 hv = ((const uint2*)zin)[(size_t)c * (DH / 4) + lane];
            float2 a = __half22float2(u2h(hv.x));
            float2 b = __half22float2(u2h(hv.y));
            az.x += v * a.x; az.y += v * a.y; az.z += v * b.x; az.w += v * b.y;
        }

        float4 x4 = u2f4(((const uint2*)g_xh)[r4]);
        float4 f;
        f.x = al * 0.5f * (az.x - zv.x) + x4.x;
        f.y = al * 0.5f * (az.y - zv.y) + x4.y;
        f.z = al * 0.5f * (az.z - zv.z) + x4.z;
        f.w = al * 0.5f * (az.w - zv.w) + x4.w;

        if (STAGE == 1) {
            float4 t1;
            t1.x = zv.x + hdt * f.x; t1.y = zv.y + hdt * f.y;
            t1.z = zv.z + hdt * f.z; t1.w = zv.w + hdt * f.w;
            ((uint2*)g_t1)[r4] = f42u(t1);
        } else if (STAGE == 2) {
            float4 zh = u2f4(((const uint2*)g_h0)[r4]);
            float4 zr = u2f4(((const uint2*)g_zl)[r4]);
            float4 z0;
            z0.x = zh.x + zr.x; z0.y = zh.y + zr.y;
            z0.z = zh.z + zr.z; z0.w = zh.w + zr.w;
            const float ih = 1.0f / 0.225f;
            float4 k1;
            k1.x = (zv.x - z0.x) * ih; k1.y = (zv.y - z0.y) * ih;
            k1.z = (zv.z - z0.z) * ih; k1.w = (zv.w - z0.w) * ih;
            float4 t2;
            t2.x = z0.x + hdt * f.x; t2.y = z0.y + hdt * f.y;
            t2.z = z0.z + hdt * f.z; t2.w = z0.w + hdt * f.w;
            ((uint2*)g_t2)[r4] = f42u(t2);
            float4 ac;
            ac.x = z0.x + dt6 * k1.x + dt3 * f.x;
            ac.y = z0.y + dt6 * k1.y + dt3 * f.y;
            ac.z = z0.z + dt6 * k1.z + dt3 * f.z;
            ac.w = z0.w + dt6 * k1.w + dt3 * f.w;
            ((float4*)g_acc)[r4] = ac;
        } else if (STAGE == 3) {
            float4 z0 = u2f4(((const uint2*)g_h0)[r4]);
            float4 t3;
            t3.x = z0.x + dt * f.x; t3.y = z0.y + dt * f.y;
            t3.z = z0.z + dt * f.z; t3.w = z0.w + dt * f.w;
            ((uint2*)g_t1)[r4] = f42u(t3);
            ((uint2*)g_kh)[r4] = f42u(f);
        } else {
            float4 ac = ((const float4*)g_acc)[r4];
            float4 k3 = u2f4(((const uint2*)g_kh)[r4]);
            float4 zn;
            zn.x = ac.x + dt3 * k3.x + dt6 * f.x;
            zn.y = ac.y + dt3 * k3.y + dt6 * f.y;
            zn.z = ac.z + dt3 * k3.z + dt6 * f.z;
            zn.w = ac.w + dt3 * k3.w + dt6 * f.w;
            if (out != nullptr) {
                ((float4*)out)[r4] = zn;
            } else {
                uint2 hh = f42u(zn);
                ((uint2*)g_h0)[r4] = hh;
                float4 h4 = u2f4(hh);
                float4 rl;
                rl.x = zn.x - h4.x; rl.y = zn.y - h4.y;
                rl.z = zn.z - h4.z; rl.w = zn.w - h4.w;
                ((uint2*)g_zl)[r4] = f42u(rl);
            }
        }
    } else {
        // -------- general fallback (never taken for given inputs) --------
        __shared__ float s0[8], s1v[8], s_al[1];
        int w = t >> 5, l = t & 31;
        for (int rr = 0; rr < RPB; ++rr) {
            int r = blockIdx.x * RPB + rr;
            const float* zin = (STAGE == 1) ? g_w0 : (STAGE == 2) ? g_w1
                             : (STAGE == 3) ? g_w2 : g_w1;
            size_t ri = (size_t)r * DD + t;
            float zv = zin[ri];
            float d0 = zv * Wih[t];
            float d1 = zv * Wih[DD + t];
            #pragma unroll
            for (int off = 16; off; off >>= 1) {
                d0 += __shfl_down_sync(0xffffffffu, d0, off);
                d1 += __shfl_down_sync(0xffffffffu, d1, off);
            }
            if (l == 0) { s0[w] = d0; s1v[w] = d1; }
            __syncthreads();
            if (t == 0) {
                float a0 = 0.0f, a1 = 0.0f;
                #pragma unroll
                for (int i = 0; i < 8; ++i) { a0 += s0[i]; a1 += s1v[i]; }
                a0 = tanhf(a0 + g_hb[2 * r]);
                a1 = tanhf(a1 + g_hb[2 * r + 1]);
                float al = g_alpha[r] * a0 + a1;
                g_alpha[r] = al;
                s_al[0] = 1.0f / (1.0f + expf(-al));
            }
            int es = g_rowptr[r], ee = g_rowptr[r + 1];
            float az = 0.0f;
            for (int i = es; i < ee; ++i) {
                unsigned long long pk = g_edges[i];
                int   c = (int)(unsigned int)(pk & 0xffffffffu);
                float v = __uint_as_float((unsigned int)(pk >> 32));
                az += v * zin[(size_t)c * DD + t];
            }
            __syncthreads();
            float f = s_al[0] * 0.5f * (az - zv) + ((t < DH) ? x[(size_t)r * DH + t] : 0.0f);
            const float* zr = zin + (size_t)r * DD;
            for (int j = 0; j < DD; ++j) f += zr[j] * g_M[j * DD + t];

            if (STAGE == 1)      { g_wk[ri] = f;          g_w1[ri] = zv + hdt * f; }
            else if (STAGE == 2) { g_wk[ri] += 2.0f * f;  g_w2[ri] = g_w0[ri] + hdt * f; }
            else if (STAGE == 3) { g_wk[ri] += 2.0f * f;  g_w1[ri] = g_w0[ri] + dt * f; }
            else {
                float zn = g_w0[ri] + dt6 * (g_wk[ri] + f);
                g_w0[ri] = zn;
                if (out != nullptr && t < DH) out[(size_t)r * DH + t] = zn;
            }
            __syncthreads();
        }
    }
}

// ------------------- launch -------------------
extern "C" void kernel_launch(void* const* d_in, const int* in_sizes, int n_in,
                              void* d_out, int out_size) {
    const float* x      = (const float*)d_in[0];
    const int*   erows  = (const int*)  d_in[1];
    const int*   ecols  = (const int*)  d_in[2];
    const float* evals  = (const float*)d_in[3];
    const float* Wih    = (const float*)d_in[4];
    const float* Whh    = (const float*)d_in[5];
    const float* bih    = (const float*)d_in[6];
    const float* bhh    = (const float*)d_in[7];
    const float* h      = (const float*)d_in[8];
    const float* alpha0 = (const float*)d_in[9];
    const float* W      = (const float*)d_in[10];
    const float* dvec   = (const float*)d_in[11];
    float* out = (float*)d_out;

    reset_all<<<(NN + 255) / 256, 256>>>();
    computeM_small<<<DD + (NN + 255) / 256, 256>>>(W, dvec, alpha0, h, Whh, bih, bhh);
    count_k<<<(EE + 255) / 256, 256>>>(erows);
    scan_initz<<<NBLK + (NN * DH / 4 + SCAN_B - 1) / SCAN_B, SCAN_B>>>(x);
    scan_bsum<<<1, 128>>>();
    scan_add_zero<<<(NN + 255) / 256, 256>>>();
    scatter_k<<<(EE + 255) / 256, 256>>>(erows, ecols, evals);

    for (int s = 0; s < 2; ++s) {
        float* last_out = (s == 1) ? out : nullptr;
        ode_eval<1><<<NB8, 256>>>(x, Wih, nullptr);
        ode_eval<2><<<NB8, 256>>>(x, Wih, nullptr);
        ode_eval<3><<<NB8, 256>>>(x, Wih, nullptr);
        ode_eval<4><<<NB8, 256>>>(x, Wih, last_out);
    }
}